// round 2
// baseline (speedup 1.0000x reference)
#include <cuda_runtime.h>

#define BB 64
#define HH 14
#define WWD 14
#define HW 196
#define CC 32
#define OO 10
#define DD 16
#define NCH 14            // hw-chunks per batch element
#define HWB (HW/NCH)      // 14 hw positions per block
#define TPB 320           // 10 warps: warp = o, lane = c
#define EPSF 1e-9f
#define LOG2PI 1.8378770664093453f

// Scratch (fully rewritten every pass -> deterministic, graph-safe)
__device__ float g_partials[BB*NCH*OO*33];   // per-block partial sums: [b][chunk][o][S0, S1[16], S2[16]]
__device__ float g_params[BB*OO*33];         // per-pass routing params:  [b][o][K, ivar[16], muinv[16]]

// ---------------------------------------------------------------------------
// Accumulate kernel. PASS==0: rr = 1/O (first iteration). PASS==1: rr from
// softmax over o of (K_o + sum_d v*muinv - 0.5*sum_d v^2*ivar).
// grid = (NCH, BB), block = 320.
// ---------------------------------------------------------------------------
template<int PASS>
__global__ void __launch_bounds__(TPB)
caps_accum(const float* __restrict__ pose,
           const float* __restrict__ act,
           const float* __restrict__ w)
{
    __shared__ float sp[HWB][CC][17];   // pose tile, padded stride 17 (conflict-free per-lane-c)
    __shared__ float sa[HWB][CC];       // activations
    __shared__ float ss[CC][11];        // softmax logits (padded)
    __shared__ float se[CC][11];        // softmax exps   (padded)

    const int b   = blockIdx.y;
    const int ch  = blockIdx.x;
    const int hw0 = ch * HWB;
    const int tid = threadIdx.x;
    const int o   = tid >> 5;    // warp id
    const int c   = tid & 31;    // lane id

    // ---- cooperative tile load -------------------------------------------
    {
        const float* src = pose + (size_t)(b * HW + hw0) * CC * 16;
        for (int idx = tid; idx < HWB * CC * 16; idx += TPB) {
            int hw_l = idx >> 9;          // /512
            int rem  = idx & 511;
            int c_l  = rem >> 4;
            int j    = rem & 15;
            sp[hw_l][c_l][j] = src[idx];
        }
        const float* asrc = act + (size_t)(b * HW + hw0) * CC;
        for (int idx = tid; idx < HWB * CC; idx += TPB) {
            sa[idx >> 5][idx & 31] = asrc[idx];
        }
    }

    // ---- per-thread constants: w[c][o][4][4] in registers ----------------
    float wr[16];
    {
        const float4* wp = reinterpret_cast<const float4*>(w + (size_t)(c * OO + o) * 16);
        #pragma unroll
        for (int q = 0; q < 4; q++) {
            float4 t = wp[q];
            wr[q*4+0] = t.x; wr[q*4+1] = t.y; wr[q*4+2] = t.z; wr[q*4+3] = t.w;
        }
    }

    float K = 0.f, iv[16], mi[16];
    if (PASS == 1) {
        const float* pp = g_params + (size_t)(b * OO + o) * 33;
        K = pp[0];
        #pragma unroll
        for (int d = 0; d < 16; d++) { iv[d] = pp[1 + d]; mi[d] = pp[17 + d]; }
    }

    float S0 = 0.f, S1[16], S2[16];
    #pragma unroll
    for (int d = 0; d < 16; d++) { S1[d] = 0.f; S2[d] = 0.f; }

    __syncthreads();

    // ---- main loop over hw positions -------------------------------------
    for (int t = 0; t < HWB; t++) {
        const int hw   = hw0 + t;
        const int h    = hw / WWD;
        const int wpos = hw % WWD;
        const float wo = (wpos + 0.5f) * (1.0f / WWD);
        const float ho = (h    + 0.5f) * (1.0f / HH);

        const float a = sa[t][c];

        // votes: v[i*4+col] = sum_j p[i*4+j] * w[o][j*4+col]  (+ coord add)
        float v[16];
        #pragma unroll
        for (int i = 0; i < 4; i++) {
            const float p0 = sp[t][c][i*4+0];
            const float p1 = sp[t][c][i*4+1];
            const float p2 = sp[t][c][i*4+2];
            const float p3 = sp[t][c][i*4+3];
            #pragma unroll
            for (int col = 0; col < 4; col++) {
                v[i*4+col] = fmaf(p0, wr[0*4+col],
                             fmaf(p1, wr[1*4+col],
                             fmaf(p2, wr[2*4+col], p3 * wr[3*4+col])));
            }
        }
        v[3] += wo;
        v[7] += ho;

        float ap;
        if (PASS == 0) {
            ap = a * 0.1f;                       // rr = 1/O
        } else {
            float e1 = 0.f, e2 = 0.f;
            #pragma unroll
            for (int d = 0; d < 16; d++) {
                const float vd = v[d];
                e1 = fmaf(vd * vd, iv[d], e1);
                e2 = fmaf(vd,      mi[d], e2);
            }
            const float s = K + e2 - 0.5f * e1;  // log(act)+ln_p
            ss[c][o] = s;
            __syncthreads();
            float m = ss[c][0];
            #pragma unroll
            for (int oo = 1; oo < OO; oo++) m = fmaxf(m, ss[c][oo]);
            const float e = __expf(s - m);
            se[c][o] = e;
            __syncthreads();
            float den = se[c][0];
            #pragma unroll
            for (int oo = 1; oo < OO; oo++) den += se[c][oo];
            ap = a * __fdividef(e, den);         // rr_p = softmax * act
        }

        S0 += ap;
        #pragma unroll
        for (int d = 0; d < 16; d++) {
            const float t1 = ap * v[d];
            S1[d] += t1;
            S2[d]  = fmaf(t1, v[d], S2[d]);
        }
    }

    // ---- reduce over c (full-warp shuffles), lane 0 writes partials ------
    #pragma unroll
    for (int off = 16; off > 0; off >>= 1) {
        S0 += __shfl_xor_sync(0xFFFFFFFFu, S0, off);
        #pragma unroll
        for (int d = 0; d < 16; d++) {
            S1[d] += __shfl_xor_sync(0xFFFFFFFFu, S1[d], off);
            S2[d] += __shfl_xor_sync(0xFFFFFFFFu, S2[d], off);
        }
    }
    if (c == 0) {
        float* dst = g_partials + (size_t)((b * NCH + ch) * OO + o) * 33;
        dst[0] = S0;
        #pragma unroll
        for (int d = 0; d < 16; d++) { dst[1 + d] = S1[d]; dst[17 + d] = S2[d]; }
    }
}

// ---------------------------------------------------------------------------
// Reduce kernel: sum partials, compute mu/var/act. FINAL==0 -> write params
// for next pass; FINAL==1 -> write outputs. grid = BB, block = 160 (o*16+d).
// ---------------------------------------------------------------------------
template<int FINAL>
__global__ void __launch_bounds__(160)
caps_reduce(const float* __restrict__ beta_a,
            const float* __restrict__ beta_u,
            float inv_temp,
            float* __restrict__ out)
{
    const int b   = blockIdx.x;
    const int tid = threadIdx.x;
    const int o   = tid >> 4;
    const int d   = tid & 15;

    float S0 = 0.f, S1 = 0.f, S2 = 0.f;
    for (int g = 0; g < NCH; g++) {
        const float* p = g_partials + (size_t)((b * NCH + g) * OO + o) * 33;
        S0 += p[0];
        S1 += p[1 + d];
        S2 += p[17 + d];
    }

    const float rs     = S0 + EPSF;
    const float inv_rs = 1.0f / rs;
    const float mu     = S1 * inv_rs;
    const float var    = fmaxf(S2 * inv_rs - mu * mu, 0.0f) + EPSF;
    const float lv     = __logf(var);
    const float ivar   = 1.0f / var;
    const float muinv  = mu * ivar;
    const float mive   = mu * muinv;

    // reduce lv, mive over the 16-lane d-group (aligned within warp)
    float sumlv = lv, summive = mive;
    #pragma unroll
    for (int off = 1; off < 16; off <<= 1) {
        sumlv   += __shfl_xor_sync(0xFFFFFFFFu, sumlv,   off);
        summive += __shfl_xor_sync(0xFFFFFFFFu, summive, off);
    }

    const float cost = rs * (16.0f * beta_u[o] + 0.5f * sumlv);
    const float x    = inv_temp * (beta_a[o] - cost);
    const float actv = 1.0f / (1.0f + __expf(-x));

    if (FINAL) {
        out[(size_t)(b * OO + o) * 16 + d] = mu;                 // pose_out
        if (d == 0) out[BB * OO * 16 + b * OO + o] = actv;       // act_out
    } else {
        float* pp = g_params + (size_t)(b * OO + o) * 33;
        pp[1 + d]  = ivar;
        pp[17 + d] = muinv;
        if (d == 0)
            pp[0] = __logf(actv + EPSF)
                  - 0.5f * (16.0f * LOG2PI + sumlv)
                  - 0.5f * summive;
    }
}

// ---------------------------------------------------------------------------
extern "C" void kernel_launch(void* const* d_in, const int* in_sizes, int n_in,
                              void* d_out, int out_size)
{
    const float* pose = (const float*)d_in[0];
    const float* act  = (const float*)d_in[1];
    const float* w    = (const float*)d_in[2];
    const float* ba   = (const float*)d_in[3];
    const float* bu   = (const float*)d_in[4];
    float* out = (float*)d_out;

    dim3 ga(NCH, BB);

    // it = 0 (inv_temp = 1)
    caps_accum<0><<<ga, TPB>>>(pose, act, w);
    caps_reduce<0><<<BB, 160>>>(ba, bu, 1.0f, out);
    // it = 1 (inv_temp = 2)
    caps_accum<1><<<ga, TPB>>>(pose, act, w);
    caps_reduce<0><<<BB, 160>>>(ba, bu, 2.0f, out);
    // it = 2 (inv_temp = 3) -> final outputs
    caps_accum<1><<<ga, TPB>>>(pose, act, w);
    caps_reduce<1><<<BB, 160>>>(ba, bu, 3.0f, out);
}